// round 17
// baseline (speedup 1.0000x reference)
#include <cuda_runtime.h>
#include <cuda_bf16.h>
#include <cstdint>
#include <math.h>

#define N_NODES 50000
#define MPAD    50048   // multiple of 128; pad rows stay zero (.bss)
#define N_EDGES 800000
#define N_GRAPHS 128
#define IN_DIM  100
#define HID     256
#define STEPS   5

// ---------------- scratch (device globals; zero-initialized, no allocation) ----
__device__ float d_h [MPAD * HID];                  // h fp32 (gather/pool/GRU-old)
__device__ float d_g [(size_t)N_NODES * 1024];      // gate pre-acts [r|z|i_n|h_n]
__device__ float d_t1[(size_t)N_NODES * (HID / 2)];
__device__ float d_pool[N_GRAPHS * 2 * HID];

// concat activation buffer: cols [0,256)=hs (gathered), [256,512)=h  (bf16 hi/lo)
__device__ __nv_bfloat16 d_cat_hi[(size_t)MPAD * 512], d_cat_lo[(size_t)MPAD * 512];
__device__ __nv_bfloat16 d_x_hi [MPAD * 128], d_x_lo [MPAD * 128];

// folded gate weights: Bcomb[s] = W_ih @ w[s]^T   [768 rows, 256 K]
__device__ __nv_bfloat16 d_bcomb_hi[STEPS * 768 * 256], d_bcomb_lo[STEPS * 768 * 256];
// Whh2 [1024 rows, 256 K]: rows 0-511 = Whh r/z, rows 768-1023 = Whh n, 512-767 unused
__device__ __nv_bfloat16 d_whh2_hi[1024 * 256], d_whh2_lo[1024 * 256];
__device__ __nv_bfloat16 d_wihs_hi[768 * 256], d_wihs_lo[768 * 256];   // W_ih split
// RAW (untransposed) ggc_w split: wraw[s][k'][j] = ggc_w[s][k'][j], K-contig along j
__device__ __nv_bfloat16 d_wraw_hi[STEPS * 256 * 256], d_wraw_lo[STEPS * 256 * 256];
__device__ __nv_bfloat16 d_wa1_hi[128 * 256], d_wa1_lo[128 * 256];
__device__ __nv_bfloat16 d_win_hi[256 * 128], d_win_lo[256 * 128];

// ---------------- CSR-by-destination (built once per call) ----------------
__device__ int d_deg [N_NODES];
__device__ int d_fill[N_NODES];
__device__ int d_offs[N_NODES + 1];
__device__ int d_eidx[N_EDGES];     // src node ids bucketed by dst

// ================= PTX helpers (sm_80-baseline only) =================
__device__ __forceinline__ uint32_t smem_u32(const void* p) {
    uint32_t a;
    asm("{ .reg .u64 t; cvta.to.shared.u64 t, %1; cvt.u32.u64 %0, t; }" : "=r"(a) : "l"(p));
    return a;
}
__device__ __forceinline__ void cp16(uint32_t s, const void* g) {
    asm volatile("cp.async.cg.shared.global [%0], [%1], 16;" :: "r"(s), "l"(g));
}
#define CP_COMMIT() asm volatile("cp.async.commit_group;" ::: "memory")
#define CP_WAIT(N)  asm volatile("cp.async.wait_group %0;" :: "n"(N) : "memory")

__device__ __forceinline__ void ldm4(uint32_t& r0, uint32_t& r1, uint32_t& r2, uint32_t& r3,
                                     uint32_t a) {
    asm volatile("ldmatrix.sync.aligned.m8n8.x4.shared.b16 {%0,%1,%2,%3}, [%4];"
                 : "=r"(r0), "=r"(r1), "=r"(r2), "=r"(r3) : "r"(a));
}
__device__ __forceinline__ void mma_bf16(float* c, const uint32_t* a, const uint32_t* b) {
    asm volatile(
        "mma.sync.aligned.m16n8k16.row.col.f32.bf16.bf16.f32 "
        "{%0,%1,%2,%3}, {%4,%5,%6,%7}, {%8,%9}, {%0,%1,%2,%3};"
        : "+f"(c[0]), "+f"(c[1]), "+f"(c[2]), "+f"(c[3])
        : "r"(a[0]), "r"(a[1]), "r"(a[2]), "r"(a[3]), "r"(b[0]), "r"(b[1]));
}
__device__ __forceinline__ uint32_t pack_hi2(__nv_bfloat16 a, __nv_bfloat16 b) {
    return ((uint32_t)__bfloat16_as_ushort(b) << 16) | (uint32_t)__bfloat16_as_ushort(a);
}
__device__ __forceinline__ uint32_t pack_bf2(float a, float b) {
    return pack_hi2(__float2bfloat16(a), __float2bfloat16(b));
}

// ================= mma.sync GEMM: C[M, N] = A[M, K] @ B[N, K]^T ================
// A bf16 hi/lo, element row stride ASTRIDE. Split: AhBh + AhBl + AlBh.
// CTA 128x128, 8 warps (4x2), warp tile 32x64, K chunk 32, double-buffered.
// GATEK: K-chunks [0,CH/2) read B1 (stride 256), chunks [CH/2,CH) read B2
//        (stride 256, k rebased); col tiles 4-5 only first half, 6-7 only second.
template <int KTOT, int ASTRIDE, bool GATEK, bool WF32, bool WBF16, bool RELU>
__global__ __launch_bounds__(256) void mma_gemm(
    const __nv_bfloat16* __restrict__ Ah, const __nv_bfloat16* __restrict__ Al,
    const __nv_bfloat16* __restrict__ Bh, const __nv_bfloat16* __restrict__ Bl,
    const __nv_bfloat16* __restrict__ B2h, const __nv_bfloat16* __restrict__ B2l,
    const float* __restrict__ bias,
    float* __restrict__ Cf, __nv_bfloat16* __restrict__ Cbh, __nv_bfloat16* __restrict__ Cbl,
    int M, int CFS, int CBS)
{
    constexpr int CH = KTOT / 32;
    constexpr int RSTRIDE = 80;          // 64B data + 16B pad per 32-elem bf16 row
    constexpr int MAT = 128 * RSTRIDE;   // 10240 B per matrix per stage
    extern __shared__ char smem[];
    const uint32_t sb = smem_u32(smem);

    const int tid = threadIdx.x;
    const int wid = tid >> 5, lane = tid & 31;
    const int warp_m = wid & 3, warp_n = wid >> 2;
    const int row0 = blockIdx.y * 128;
    const int ncol0 = blockIdx.x * 128;

    int c_begin = 0, c_end = CH;
    if constexpr (GATEK) {
        if (blockIdx.x >= 6) c_begin = CH / 2;       // h_n rows: K[256:512)
        else if (blockIdx.x >= 4) c_end = CH / 2;    // i_n rows: K[0:256)
    }

    float acc[2][8][4];
#pragma unroll
    for (int tm = 0; tm < 2; tm++)
#pragma unroll
        for (int nt = 0; nt < 8; nt++)
#pragma unroll
            for (int c = 0; c < 4; c++) acc[tm][nt][c] = 0.f;

    auto load_stage = [&](int c, int st) {
        const int k0 = c * 32;
        const uint32_t base = sb + st * (4 * MAT);
#pragma unroll
        for (int i = 0; i < 2; i++) {
            int l = tid + i * 256;       // 512 uint4 per matrix
            int row = l >> 2, q = l & 3;
            uint32_t so = (uint32_t)(row * RSTRIDE + q * 16);
            size_t ea = (size_t)(row0 + row) * ASTRIDE + k0 + q * 8;
            cp16(base + so,       Ah + ea);
            cp16(base + MAT + so, Al + ea);
            if constexpr (GATEK) {
                const bool first = (c < CH / 2);
                const __nv_bfloat16* Bh_ = first ? Bh : B2h;
                const __nv_bfloat16* Bl_ = first ? Bl : B2l;
                int kk = first ? k0 : (k0 - KTOT / 2);
                size_t eb = (size_t)(ncol0 + row) * 256 + kk + q * 8;
                cp16(base + 2 * MAT + so, Bh_ + eb);
                cp16(base + 3 * MAT + so, Bl_ + eb);
            } else {
                size_t eb = (size_t)(ncol0 + row) * KTOT + k0 + q * 8;
                cp16(base + 2 * MAT + so, Bh + eb);
                cp16(base + 3 * MAT + so, Bl + eb);
            }
        }
    };

    load_stage(c_begin, c_begin & 1);
    CP_COMMIT();

    const int ar = (lane & 7) + ((lane >> 3) & 1) * 8;
    const int akh = lane >> 4;
    const int bn = (lane >> 4);
    const int bk = (lane >> 3) & 1;

    for (int c = c_begin; c < c_end; c++) {
        const int st = c & 1;
        if (c + 1 < c_end) {
            load_stage(c + 1, st ^ 1);
            CP_COMMIT();
            CP_WAIT(1);
        } else {
            CP_WAIT(0);
        }
        __syncthreads();

        const uint32_t base = sb + st * (4 * MAT);
#pragma unroll
        for (int j = 0; j < 2; j++) {    // two k16 per chunk
            uint32_t ah[2][4], al[2][4];
#pragma unroll
            for (int tm = 0; tm < 2; tm++) {
                uint32_t ao = base + (uint32_t)((warp_m * 32 + tm * 16 + ar) * RSTRIDE +
                                                j * 32 + akh * 16);
                ldm4(ah[tm][0], ah[tm][1], ah[tm][2], ah[tm][3], ao);
                ldm4(al[tm][0], al[tm][1], al[tm][2], al[tm][3], ao + MAT);
            }
            uint32_t bh[4][4], bl[4][4];
#pragma unroll
            for (int q = 0; q < 4; q++) {
                int nrow = warp_n * 64 + (2 * q + bn) * 8 + (lane & 7);
                uint32_t bo = base + 2 * MAT +
                              (uint32_t)(nrow * RSTRIDE + j * 32 + bk * 16);
                ldm4(bh[q][0], bh[q][1], bh[q][2], bh[q][3], bo);
                ldm4(bl[q][0], bl[q][1], bl[q][2], bl[q][3], bo + MAT);
            }
#pragma unroll
            for (int tm = 0; tm < 2; tm++)
#pragma unroll
                for (int nt = 0; nt < 8; nt++) {
                    int q = nt >> 1, o = (nt & 1) * 2;
                    mma_bf16(acc[tm][nt], ah[tm], &bh[q][o]);
                    mma_bf16(acc[tm][nt], ah[tm], &bl[q][o]);
                    mma_bf16(acc[tm][nt], al[tm], &bh[q][o]);
                }
        }
        __syncthreads();
    }

    // ---- epilogue ----
#pragma unroll
    for (int tm = 0; tm < 2; tm++) {
        int rbase = row0 + warp_m * 32 + tm * 16 + (lane >> 2);
#pragma unroll
        for (int half = 0; half < 2; half++) {
            int row_g = rbase + half * 8;
            if (row_g >= M) continue;
#pragma unroll
            for (int nt = 0; nt < 8; nt++) {
                int col = ncol0 + warp_n * 64 + nt * 8 + (lane & 3) * 2;
                float v0 = acc[tm][nt][half * 2 + 0];
                float v1 = acc[tm][nt][half * 2 + 1];
                if (bias) { v0 += bias[col]; v1 += bias[col + 1]; }
                if (RELU) { v0 = fmaxf(v0, 0.f); v1 = fmaxf(v1, 0.f); }
                if (WF32)
                    *(float2*)(Cf + (size_t)row_g * CFS + col) = make_float2(v0, v1);
                if (WBF16) {
                    __nv_bfloat16 h0 = __float2bfloat16(v0);
                    __nv_bfloat16 h1 = __float2bfloat16(v1);
                    float l0 = v0 - __bfloat162float(h0);
                    float l1 = v1 - __bfloat162float(h1);
                    *(uint32_t*)(Cbh + (size_t)row_g * CBS + col) = pack_hi2(h0, h1);
                    *(uint32_t*)(Cbl + (size_t)row_g * CBS + col) = pack_bf2(l0, l1);
                }
            }
        }
    }
}

// ================= CSR build (once per call) =================
__global__ void zero_csr_kernel(int* deg, int* fill) {
    int i = blockIdx.x * blockDim.x + threadIdx.x;
    if (i < N_NODES) { deg[i] = 0; fill[i] = 0; }
}
__global__ void hist_kernel(const int* __restrict__ dst, int* __restrict__ deg) {
    int e = blockIdx.x * blockDim.x + threadIdx.x;
    if (e < N_EDGES) atomicAdd(&deg[dst[e]], 1);
}
__global__ __launch_bounds__(1024) void scan_kernel(const int* __restrict__ deg,
                                                    int* __restrict__ offs) {
    __shared__ int part[1024];
    const int tid = threadIdx.x;
    const int per = (N_NODES + 1023) / 1024;  // 49
    int s0 = tid * per;
    int s1 = s0 + per; if (s1 > N_NODES) s1 = N_NODES;
    int sum = 0;
    for (int i = s0; i < s1; i++) sum += deg[i];
    part[tid] = sum;
    __syncthreads();
    for (int off = 1; off < 1024; off <<= 1) {
        int v = 0;
        if (tid >= off) v = part[tid - off];
        __syncthreads();
        if (tid >= off) part[tid] += v;
        __syncthreads();
    }
    int run = (tid == 0) ? 0 : part[tid - 1];
    for (int i = s0; i < s1; i++) { offs[i] = run; run += deg[i]; }
    if (tid == 1023) offs[N_NODES] = run;
}
__global__ void fill_kernel(const int* __restrict__ src, const int* __restrict__ dst,
                            const int* __restrict__ offs, int* __restrict__ fill,
                            int* __restrict__ eidx) {
    int e = blockIdx.x * blockDim.x + threadIdx.x;
    if (e >= N_EDGES) return;
    int d = dst[e];
    int pos = offs[d] + atomicAdd(&fill[d], 1);
    eidx[pos] = src[e];
}

// === atomic-free gather, split into cat[0:256): hs[n] = sum h[src[e]] ========
__global__ __launch_bounds__(128) void gather_kernel(
    const float* __restrict__ h, const int* __restrict__ offs,
    const int* __restrict__ eidx, __nv_bfloat16* __restrict__ ch,
    __nv_bfloat16* __restrict__ cl) {
    int node = blockIdx.x;
    int t = threadIdx.x;                   // 128 threads, float2 each
    int lo = offs[node], hi = offs[node + 1];
    float2 acc = make_float2(0.f, 0.f);
    for (int j = lo; j < hi; j++) {
        int s = __ldg(eidx + j);
        float2 v = *(const float2*)(h + (size_t)s * HID + t * 2);
        acc.x += v.x; acc.y += v.y;
    }
    size_t ob = (size_t)node * 512 + t * 2;
    __nv_bfloat16 q0 = __float2bfloat16(acc.x), q1 = __float2bfloat16(acc.y);
    *(uint32_t*)(ch + ob) = pack_hi2(q0, q1);
    *(uint32_t*)(cl + ob) = pack_bf2(acc.x - __bfloat162float(q0),
                                     acc.y - __bfloat162float(q1));
}

// ================= weight conversion kernels =================
__device__ __forceinline__ void split_store(float v, __nv_bfloat16* ph, __nv_bfloat16* pl) {
    __nv_bfloat16 h = __float2bfloat16(v);
    *ph = h;
    *pl = __float2bfloat16(v - __bfloat162float(h));
}
// elementwise fp32 -> bf16 hi/lo (row-major preserved)
__global__ void conv_pair4(const float4* __restrict__ src, uint2* __restrict__ dh,
                           uint2* __restrict__ dl, long n4) {
    long i = (long)blockIdx.x * blockDim.x + threadIdx.x;
    if (i >= n4) return;
    float4 v = src[i];
    __nv_bfloat16 h0 = __float2bfloat16(v.x), h1 = __float2bfloat16(v.y);
    __nv_bfloat16 h2 = __float2bfloat16(v.z), h3 = __float2bfloat16(v.w);
    uint2 uh, ul;
    uh.x = pack_hi2(h0, h1);
    uh.y = pack_hi2(h2, h3);
    ul.x = pack_bf2(v.x - __bfloat162float(h0), v.y - __bfloat162float(h1));
    ul.y = pack_bf2(v.z - __bfloat162float(h2), v.w - __bfloat162float(h3));
    dh[i] = uh;
    dl[i] = ul;
}
// Whh2 [1024,256]: rows 0-511 <- Whh rows 0-511; rows 768-1023 <- Whh rows 512-767
__global__ void conv_whh2(const float* __restrict__ whh, __nv_bfloat16* dh, __nv_bfloat16* dl) {
    int idx = blockIdx.x * blockDim.x + threadIdx.x;
    if (idx >= 1024 * 256) return;
    int n = idx >> 8, k = idx & 255;
    float v = 0.f;
    if (n < 512)       v = whh[n * 256 + k];
    else if (n >= 768) v = whh[(n - 256) * 256 + k];
    split_store(v, dh + idx, dl + idx);
}
// Wa1[k(256)][n(128)] -> wa1t[n][k]
__global__ void conv_wa1(const float* __restrict__ src, __nv_bfloat16* dh, __nv_bfloat16* dl) {
    int idx = blockIdx.x * blockDim.x + threadIdx.x;
    if (idx >= 128 * 256) return;
    int nn = idx >> 8, kk = idx & 255;
    split_store(src[kk * 128 + nn], dh + idx, dl + idx);
}
// W_in[k(100)][n(256)] -> wint[n][k(128 padded)]
__global__ void conv_win(const float* __restrict__ src, __nv_bfloat16* dh, __nv_bfloat16* dl) {
    int idx = blockIdx.x * blockDim.x + threadIdx.x;
    if (idx >= 256 * 128) return;
    int nn = idx >> 7, kk = idx & 127;
    split_store((kk < IN_DIM) ? src[kk * 256 + nn] : 0.f, dh + idx, dl + idx);
}
// x[r][100] -> x_hi/lo[r][128 padded]
__global__ void conv_x(const float* __restrict__ x, __nv_bfloat16* dh, __nv_bfloat16* dl) {
    long idx = (long)blockIdx.x * blockDim.x + threadIdx.x;
    if (idx >= (long)N_NODES * 128) return;
    int r = (int)(idx >> 7), k = (int)(idx & 127);
    split_store((k < IN_DIM) ? x[(size_t)r * IN_DIM + k] : 0.f, dh + idx, dl + idx);
}

// ================= GRU elementwise: reads g[·,1024], writes h + cat split ======
__global__ void gru_kernel(const float* __restrict__ g,
                           const float* __restrict__ b_ih, const float* __restrict__ b_hh,
                           float* __restrict__ h, __nv_bfloat16* __restrict__ ch,
                           __nv_bfloat16* __restrict__ cl) {
    long idx = (long)blockIdx.x * blockDim.x + threadIdx.x;
    if (idx >= (long)N_NODES * 64) return;
    int n = (int)(idx >> 6);
    int d = (int)(idx & 63) << 2;
    size_t gb = (size_t)n * 1024 + d;
    float4 rs  = *(const float4*)(g + gb);
    float4 zs  = *(const float4*)(g + gb + 256);
    float4 inn = *(const float4*)(g + gb + 512);
    float4 hnn = *(const float4*)(g + gb + 768);
    float4 bir = *(const float4*)(b_ih + d);
    float4 biz = *(const float4*)(b_ih + 256 + d);
    float4 bin_ = *(const float4*)(b_ih + 512 + d);
    float4 bhr = *(const float4*)(b_hh + d);
    float4 bhz = *(const float4*)(b_hh + 256 + d);
    float4 bhn = *(const float4*)(b_hh + 512 + d);
    size_t hb = (size_t)n * HID + d;
    float4 hv = *(const float4*)(h + hb);
    float o[4];
#pragma unroll
    for (int c = 0; c < 4; c++) {
        float r = 1.f / (1.f + expf(-(((const float*)&rs)[c] + ((const float*)&bir)[c] +
                                      ((const float*)&bhr)[c])));
        float z = 1.f / (1.f + expf(-(((const float*)&zs)[c] + ((const float*)&biz)[c] +
                                      ((const float*)&bhz)[c])));
        float i_n = ((const float*)&inn)[c] + ((const float*)&bin_)[c];
        float h_n = ((const float*)&hnn)[c] + ((const float*)&bhn)[c];
        float nn = tanhf(i_n + r * h_n);
        o[c] = (1.f - z) * nn + z * ((const float*)&hv)[c];
    }
    *(float4*)(h + hb) = make_float4(o[0], o[1], o[2], o[3]);
    size_t cb = (size_t)n * 512 + 256 + d;
    __nv_bfloat16 q0 = __float2bfloat16(o[0]), q1 = __float2bfloat16(o[1]);
    __nv_bfloat16 q2 = __float2bfloat16(o[2]), q3 = __float2bfloat16(o[3]);
    uint2 uh, ul;
    uh.x = pack_hi2(q0, q1);
    uh.y = pack_hi2(q2, q3);
    ul.x = pack_bf2(o[0] - __bfloat162float(q0), o[1] - __bfloat162float(q1));
    ul.y = pack_bf2(o[2] - __bfloat162float(q2), o[3] - __bfloat162float(q3));
    *(uint2*)(ch + cb) = uh;
    *(uint2*)(cl + cb) = ul;
}

// h = relu(h), re-emit split into cat(+256)
__global__ void relu_h_kernel(float* __restrict__ h, __nv_bfloat16* __restrict__ ch,
                              __nv_bfloat16* __restrict__ cl) {
    long idx = (long)blockIdx.x * blockDim.x + threadIdx.x;
    if (idx >= (long)N_NODES * 64) return;
    int n = (int)(idx >> 6);
    int d = (int)(idx & 63) << 2;
    size_t hb = (size_t)n * HID + d;
    float4 v = *(const float4*)(h + hb);
    v.x = fmaxf(v.x, 0.f); v.y = fmaxf(v.y, 0.f);
    v.z = fmaxf(v.z, 0.f); v.w = fmaxf(v.w, 0.f);
    *(float4*)(h + hb) = v;
    size_t cb = (size_t)n * 512 + 256 + d;
    __nv_bfloat16 q0 = __float2bfloat16(v.x), q1 = __float2bfloat16(v.y);
    __nv_bfloat16 q2 = __float2bfloat16(v.z), q3 = __float2bfloat16(v.w);
    uint2 uh, ul;
    uh.x = pack_hi2(q0, q1);
    uh.y = pack_hi2(q2, q3);
    ul.x = pack_bf2(v.x - __bfloat162float(q0), v.y - __bfloat162float(q1));
    ul.y = pack_bf2(v.z - __bfloat162float(q2), v.w - __bfloat162float(q3));
    *(uint2*)(ch + cb) = uh;
    *(uint2*)(cl + cb) = ul;
}

// a = sigmoid(t1 @ Wa2 + ba2)
__global__ void attn_a_kernel(const float* __restrict__ t1, const float* __restrict__ Wa2,
                              const float* __restrict__ ba2, float* __restrict__ a) {
    long idx = (long)blockIdx.x * blockDim.x + threadIdx.x;
    int warp = (int)(idx >> 5);
    int lane = (int)(idx & 31);
    if (warp >= N_NODES) return;
    float s = 0.f;
#pragma unroll
    for (int k = lane; k < HID / 2; k += 32) s += t1[(size_t)warp * (HID / 2) + k] * Wa2[k];
#pragma unroll
    for (int o = 16; o > 0; o >>= 1) s += __shfl_xor_sync(0xFFFFFFFFu, s, o);
    if (lane == 0) a[warp] = 1.f / (1.f + expf(-(s + ba2[0])));
}

__global__ void pool_kernel(const float* __restrict__ h, const float* __restrict__ a,
                            const int* __restrict__ batch, float* __restrict__ pool) {
    int g = blockIdx.x;
    int d = threadIdx.x;
    __shared__ int s_lo, s_hi;
    if (d == 0) {
        int lo = 0, hi = N_NODES;
        while (lo < hi) { int mid = (lo + hi) >> 1; if (batch[mid] < g) lo = mid + 1; else hi = mid; }
        s_lo = lo;
        lo = 0; hi = N_NODES;
        while (lo < hi) { int mid = (lo + hi) >> 1; if (batch[mid] < g + 1) lo = mid + 1; else hi = mid; }
        s_hi = lo;
    }
    __syncthreads();
    int lo = s_lo, hi = s_hi;
    float sum = 0.f, mx = 0.f;  // wx >= 0 so 0-init max matches ref
    for (int i = lo; i < hi; i++) {
        float w = h[(size_t)i * HID + d] * a[i];
        sum += w;
        mx = fmaxf(mx, w);
    }
    int cnt = hi - lo;
    pool[(size_t)g * 2 * HID + d] = sum / (float)(cnt > 1 ? cnt : 1);
    pool[(size_t)g * 2 * HID + HID + d] = (cnt > 0) ? mx : 0.f;
}

__global__ void classifier_kernel(const float* __restrict__ pool,
                                  const float* __restrict__ Wc1, const float* __restrict__ bc1,
                                  const float* __restrict__ Wc2, const float* __restrict__ bc2,
                                  const float* __restrict__ Wc3, const float* __restrict__ bc3,
                                  float* __restrict__ preds) {
    int g = blockIdx.x;
    int t = threadIdx.x;
    __shared__ float sg[2 * HID];
    __shared__ float t1[HID];
    __shared__ float t2[HID / 2];
    sg[t] = pool[(size_t)g * 2 * HID + t];
    sg[t + HID] = pool[(size_t)g * 2 * HID + HID + t];
    __syncthreads();
    {
        float acc = bc1[t];
        for (int k = 0; k < 2 * HID; k++) acc += sg[k] * Wc1[(size_t)k * HID + t];
        t1[t] = fmaxf(acc, 0.f);
    }
    __syncthreads();
    if (t < HID / 2) {
        float acc = bc2[t];
        for (int k = 0; k < HID; k++) acc += t1[k] * Wc2[(size_t)k * (HID / 2) + t];
        t2[t] = fmaxf(acc, 0.f);
    }
    __syncthreads();
    if (t < 2) {
        float acc = bc3[t];
        for (int k = 0; k < HID / 2; k++) acc += t2[k] * Wc3[(size_t)k * 2 + t];
        preds[g * 2 + t] = acc;
    }
}

// ================= launch =================
extern "C" void kernel_launch(void* const* d_in, const int* in_sizes, int n_in,
                              void* d_out, int out_size) {
    const float* x     = (const float*)d_in[0];
    const int*   edge  = (const int*)d_in[1];
    const int*   batch = (const int*)d_in[2];
    const float* W_in  = (const float*)d_in[3];
    const float* b_in  = (const float*)d_in[4];
    const float* ggc_w = (const float*)d_in[5];
    const float* W_ih  = (const float*)d_in[6];
    const float* W_hh  = (const float*)d_in[7];
    const float* b_ih  = (const float*)d_in[8];
    const float* b_hh  = (const float*)d_in[9];
    const float* Wa1   = (const float*)d_in[10];
    const float* ba1   = (const float*)d_in[11];
    const float* Wa2   = (const float*)d_in[12];
    const float* ba2   = (const float*)d_in[13];
    const float* Wc1   = (const float*)d_in[14];
    const float* bc1   = (const float*)d_in[15];
    const float* Wc2   = (const float*)d_in[16];
    const float* bc2   = (const float*)d_in[17];
    const float* Wc3   = (const float*)d_in[18];
    const float* bc3   = (const float*)d_in[19];

    float* out   = (float*)d_out;
    float* preds = out;
    float* a_out = out + N_GRAPHS * 2;

    float *h, *g, *t1, *pool;
    __nv_bfloat16 *cat_hi, *cat_lo, *x_hi, *x_lo;
    __nv_bfloat16 *bcomb_hi, *bcomb_lo, *whh2_hi, *whh2_lo, *wihs_hi, *wihs_lo;
    __nv_bfloat16 *wraw_hi, *wraw_lo, *wa1_hi, *wa1_lo, *win_hi, *win_lo;
    int *deg, *fill, *offs, *eidx;
    cudaGetSymbolAddress((void**)&h, d_h);
    cudaGetSymbolAddress((void**)&g, d_g);
    cudaGetSymbolAddress((void**)&t1, d_t1);
    cudaGetSymbolAddress((void**)&pool, d_pool);
    cudaGetSymbolAddress((void**)&cat_hi, d_cat_hi);
    cudaGetSymbolAddress((void**)&cat_lo, d_cat_lo);
    cudaGetSymbolAddress((void**)&x_hi, d_x_hi);
    cudaGetSymbolAddress((void**)&x_lo, d_x_lo);
    cudaGetSymbolAddress((void**)&bcomb_hi, d_bcomb_hi);
    cudaGetSymbolAddress((void**)&bcomb_lo, d_bcomb_lo);
    cudaGetSymbolAddress((void**)&whh2_hi, d_whh2_hi);
    cudaGetSymbolAddress((void**)&whh2_lo, d_whh2_lo);
    cudaGetSymbolAddress((void**)&wihs_hi, d_wihs_hi);
    cudaGetSymbolAddress((void**)&wihs_lo, d_wihs_lo);
    cudaGetSymbolAddress((void**)&wraw_hi, d_wraw_hi);
    cudaGetSymbolAddress((void**)&wraw_lo, d_wraw_lo);
    cudaGetSymbolAddress((void**)&wa1_hi, d_wa1_hi);
    cudaGetSymbolAddress((void**)&wa1_lo, d_wa1_lo);
    cudaGetSymbolAddress((void**)&win_hi, d_win_hi);
    cudaGetSymbolAddress((void**)&win_lo, d_win_lo);
    cudaGetSymbolAddress((void**)&deg, d_deg);
    cudaGetSymbolAddress((void**)&fill, d_fill);
    cudaGetSymbolAddress((void**)&offs, d_offs);
    cudaGetSymbolAddress((void**)&eidx, d_eidx);

    const int* src = edge;
    const int* dst = edge + N_EDGES;

    const int SMEM = 2 * 4 * (128 * 80);  // 81920 B
    cudaFuncSetAttribute(mma_gemm<128, 128, false, true, true, true>,
                         cudaFuncAttributeMaxDynamicSharedMemorySize, SMEM);
    cudaFuncSetAttribute(mma_gemm<256, 256, false, false, true, false>,
                         cudaFuncAttributeMaxDynamicSharedMemorySize, SMEM);
    cudaFuncSetAttribute(mma_gemm<512, 512, true, true, false, false>,
                         cudaFuncAttributeMaxDynamicSharedMemorySize, SMEM);
    cudaFuncSetAttribute(mma_gemm<256, 512, false, true, false, true>,
                         cudaFuncAttributeMaxDynamicSharedMemorySize, SMEM);

    const int MT = (N_NODES + 127) / 128;  // 391

    // ---- CSR build (graph constant within a call) ----
    zero_csr_kernel<<<(N_NODES + 255) / 256, 256>>>(deg, fill);
    hist_kernel<<<(N_EDGES + 255) / 256, 256>>>(dst, deg);
    scan_kernel<<<1, 1024>>>(deg, offs);
    fill_kernel<<<(N_EDGES + 255) / 256, 256>>>(src, dst, offs, fill, eidx);

    // ---- weight / input conversions ----
    conv_pair4<<<(768 * 256 / 4 + 255) / 256, 256>>>(
        (const float4*)W_ih, (uint2*)wihs_hi, (uint2*)wihs_lo, 768 * 256 / 4);
    conv_whh2<<<(1024 * 256 + 255) / 256, 256>>>(W_hh, whh2_hi, whh2_lo);
    // RAW ggc_w split (no transpose): rows k', cols j — B operand for the fold
    conv_pair4<<<(STEPS * 65536 / 4 + 255) / 256, 256>>>(
        (const float4*)ggc_w, (uint2*)wraw_hi, (uint2*)wraw_lo, STEPS * 65536 / 4);
    conv_wa1<<<(128 * 256 + 255) / 256, 256>>>(Wa1, wa1_hi, wa1_lo);
    conv_win<<<(256 * 128 + 255) / 256, 256>>>(W_in, win_hi, win_lo);
    {
        long tot = (long)N_NODES * 128;
        conv_x<<<(unsigned)((tot + 255) / 256), 256>>>(x, x_hi, x_lo);
    }

    // ---- fold: Bcomb[s][m,k'] = sum_j W_ih[m,j] * w[s][k',j]  (= W_ih @ w^T) ----
    for (int s = 0; s < STEPS; s++) {
        mma_gemm<256, 256, false, false, true, false><<<dim3(2, 6), 256, SMEM>>>(
            wihs_hi, wihs_lo,
            wraw_hi + (size_t)s * 65536, wraw_lo + (size_t)s * 65536,
            nullptr, nullptr, nullptr,
            nullptr, bcomb_hi + (size_t)s * 768 * 256, bcomb_lo + (size_t)s * 768 * 256,
            768, 0, 256);
    }

    // ---- input projection: h = relu(x @ W_in + b_in); split into cat[+256] ----
    mma_gemm<128, 128, false, true, true, true><<<dim3(2, MT), 256, SMEM>>>(
        x_hi, x_lo, win_hi, win_lo, nullptr, nullptr, b_in,
        h, cat_hi + 256, cat_lo + 256, N_NODES, HID, 512);

    for (int s = 0; s < STEPS; s++) {
        // hs -> cat cols [0,256)  (CSR gather, direct bf16 split)
        gather_kernel<<<N_NODES, 128>>>(h, offs, eidx, cat_hi, cat_lo);
        // g = cat @ [Bcomb[s] | Whh2]^T  (GATEK: per-tile K ranges)
        mma_gemm<512, 512, true, true, false, false><<<dim3(8, MT), 256, SMEM>>>(
            cat_hi, cat_lo,
            bcomb_hi + (size_t)s * 768 * 256, bcomb_lo + (size_t)s * 768 * 256,
            whh2_hi, whh2_lo, nullptr,
            g, nullptr, nullptr, N_NODES, 1024, 0);
        // GRU: h = (1-z)*tanh(i_n + r*h_n) + z*h ; re-split into cat[+256]
        {
            long tot = (long)N_NODES * 64;
            gru_kernel<<<(unsigned)((tot + 255) / 256), 256>>>(
                g, b_ih, b_hh, h, cat_hi, cat_lo);
        }
    }

    {
        long tot = (long)N_NODES * 64;
        relu_h_kernel<<<(unsigned)((tot + 255) / 256), 256>>>(h, cat_hi, cat_lo);
    }

    // attention: t1 = relu(h @ Wa1 + ba1)   (A = cat cols [256,512))
    mma_gemm<256, 512, false, true, false, true><<<dim3(1, MT), 256, SMEM>>>(
        cat_hi + 256, cat_lo + 256, wa1_hi, wa1_lo, nullptr, nullptr, ba1,
        t1, nullptr, nullptr, N_NODES, HID / 2, 0);
    {
        long tot = (long)N_NODES * 32;
        attn_a_kernel<<<(unsigned)((tot + 255) / 256), 256>>>(t1, Wa2, ba2, a_out);
    }

    pool_kernel<<<N_GRAPHS, HID>>>(h, a_out, batch, pool);
    classifier_kernel<<<N_GRAPHS, 256>>>(pool, Wc1, bc1, Wc2, bc2, Wc3, bc3, preds);
}